// round 14
// baseline (speedup 1.0000x reference)
#include <cuda_runtime.h>
#include <cuda_bf16.h>
#include <cuda_fp16.h>
#include <mma.h>
#include <math.h>
#include <stdint.h>

using namespace nvcuda;

#define BATCH 4
#define CH    256
#define CKDIM 64
#define NPIX  4096
#define EPS   1e-5f
#define LDT   72            // bf16 smem tile leading dim (qk/pv)
#define PJ_LDA 136          // projections: col-major A ld (bf16)

#define DINL __device__ __forceinline__

// ---------------- device scratch (static, allocation-free) ----------------
__device__ __align__(16) float g_scale[CH];
__device__ __align__(16) float g_shift[CH];
__device__ __align__(16) float g_sx  [BATCH * CH];
__device__ __align__(16) float g_base[BATCH * CH];                        // alpha*0.5*SumV
__device__ __align__(16) float g_Wqt [CH * CKDIM];                        // BN-folded, [c][k]
__device__ __align__(16) float g_Wkt [CH * CKDIM];
__device__ __align__(16) float g_bq  [CKDIM];
__device__ __align__(16) float g_bk  [CKDIM];
__device__ __align__(16) float g_Wdt [CH * CH];                           // Wd^T, [c][d]
__device__ __align__(16) float g_Zrow[BATCH * NPIX];                      // sum_j exp(s)
__device__ __align__(16) __nv_bfloat16 g_Qb[BATCH * NPIX * CKDIM];        // [b][i][64]
__device__ __align__(16) __nv_bfloat16 g_Kb[BATCH * NPIX * CKDIM];        // [b][j][64]
__device__ __align__(16) __nv_bfloat16 g_VH[(size_t)BATCH * CH * NPIX];   // [b][c][n]
__device__ __align__(16) __half        g_S [(size_t)BATCH * NPIX * NPIX]; // fp16 scores

// ---------------- streams/events (static init: no device mem alloc) --------
static cudaStream_t g_s2, g_sB[BATCH];
static cudaEvent_t  g_evRoot, g_evW, g_evJ, g_evB[BATCH];
static struct _StrInit {
    _StrInit() {
        cudaStreamCreateWithFlags(&g_s2, cudaStreamNonBlocking);
        cudaEventCreateWithFlags(&g_evRoot, cudaEventDisableTiming);
        cudaEventCreateWithFlags(&g_evW, cudaEventDisableTiming);
        cudaEventCreateWithFlags(&g_evJ, cudaEventDisableTiming);
        for (int b = 0; b < BATCH; ++b) {
            cudaStreamCreateWithFlags(&g_sB[b], cudaStreamNonBlocking);
            cudaEventCreateWithFlags(&g_evB[b], cudaEventDisableTiming);
        }
    }
} g_strInit;

// ---------------- helpers ----------------
DINL uint32_t smem_u32(const void* p) {
    uint32_t a;
    asm("{ .reg .u64 t; cvta.to.shared.u64 t, %1; cvt.u32.u64 %0, t; }"
        : "=r"(a) : "l"(p));
    return a;
}
DINL void cpa16(uint32_t dst, const void* src) {
    asm volatile("cp.async.cg.shared.global [%0], [%1], 16;"
                 :: "r"(dst), "l"(src) : "memory");
}
DINL void cpa_commit() { asm volatile("cp.async.commit_group;" ::: "memory"); }
template<int N> DINL void cpa_wait() {
    asm volatile("cp.async.wait_group %0;" :: "n"(N) : "memory");
}
DINL float tanh_fast(float x) {
    float y;
    asm("tanh.approx.f32 %0, %1;" : "=f"(y) : "f"(x));
    return y;
}

// ---------------- kernel 0: fold BN ----------------
__global__ void prep_kernel(const float* __restrict__ gamma,
                            const float* __restrict__ beta,
                            const float* __restrict__ mean,
                            const float* __restrict__ var) {
    int c = threadIdx.x;
    if (c < CH) {
        float s = gamma[c] * rsqrtf(var[c] + EPS);
        g_scale[c] = s;
        g_shift[c] = beta[c] - mean[c] * s;
    }
}

// ---------------- kernel 0z: zero Z accumulators ----------------------------
__global__ void zeroz_kernel() {
    g_Zrow[blockIdx.x * 1024 + threadIdx.x] = 0.f;
}

// ---------------- kernel 0a: fold BN into Wb/Wc, transpose -> [c][k] --------
__global__ void foldw_kernel(const float* __restrict__ Wb,
                             const float* __restrict__ bb,
                             const float* __restrict__ Wc,
                             const float* __restrict__ bc) {
    const int k = blockIdx.x, which = blockIdx.y;
    const float* W  = which ? Wc : Wb;
    const float* bi = which ? bc : bb;
    float* Wt = which ? g_Wkt : g_Wqt;
    float* bo = which ? g_bk  : g_bq;
    const int c = threadIdx.x;
    float w = W[(size_t)k * CH + c];
    Wt[c * CKDIM + k] = w * g_scale[c];
    float sh = w * g_shift[c];
    #pragma unroll
    for (int o = 16; o; o >>= 1) sh += __shfl_xor_sync(0xffffffffu, sh, o);
    __shared__ float red[8];
    if ((c & 31) == 0) red[c >> 5] = sh;
    __syncthreads();
    if (c == 0) {
        float tot = 0.f;
        #pragma unroll
        for (int w8 = 0; w8 < 8; ++w8) tot += red[w8];
        bo[k] = bi[k] + tot;
    }
}

// ---------------- kernel 0e: transpose Wd -> [c][d] -------------------------
__global__ void transwd_kernel(const float* __restrict__ Wd) {
    const int d = blockIdx.x, c = threadIdx.x;
    g_Wdt[(size_t)c * CH + d] = Wd[(size_t)d * CH + c];
}

// ---------------- kernel 0b: column sums of x -> sx[b][c] -------------------
__global__ void colsum_kernel(const float* __restrict__ x) {
    const int c = blockIdx.x, b = blockIdx.y;
    const float* row = x + ((size_t)b * CH + c) * NPIX;
    const int t = threadIdx.x;
    float s = 0.f;
    #pragma unroll
    for (int q = 0; q < 16; ++q) s += row[t + q * 256];
    #pragma unroll
    for (int o = 16; o; o >>= 1) s += __shfl_xor_sync(0xffffffffu, s, o);
    __shared__ float ws[8];
    if ((t & 31) == 0) ws[t >> 5] = s;
    __syncthreads();
    if (t == 0) {
        float tot = 0.f;
        #pragma unroll
        for (int w = 0; w < 8; ++w) tot += ws[w];
        g_sx[b * CH + c] = tot;
    }
}

// ---------------- kernel 0c: base[b][c] = alpha*0.5*(Wd[c,:]·sx[b,:] + N*bd) -
__global__ void sumv_kernel(const float* __restrict__ Wd,
                            const float* __restrict__ bd,
                            const float* __restrict__ alpha) {
    const int b = blockIdx.x;
    const int c = threadIdx.x;
    __shared__ float sxs[CH];
    sxs[c] = g_sx[b * CH + c];
    __syncthreads();
    float dot = 0.f;
    const float* wr = Wd + (size_t)c * CH;
    #pragma unroll 8
    for (int k = 0; k < CH; ++k) dot += wr[k] * sxs[k];
    g_base[b * CH + c] = alpha[0] * 0.5f * (dot + (float)NPIX * bd[c]);
}

// ---------------- kernel 1a: Q & K projections via wmma (per batch) ---------
__global__ __launch_bounds__(256) void projqk_kernel(const float* __restrict__ x1,
                                                     const float* __restrict__ x2,
                                                     __nv_bfloat16* __restrict__ Qo,
                                                     __nv_bfloat16* __restrict__ Ko,
                                                     int b) {
    __shared__ __align__(16) char sm[35840];
    __nv_bfloat16* As = (__nv_bfloat16*)sm;             // col-major (n x c), ld=PJ_LDA
    __nv_bfloat16* Bs = (__nv_bfloat16*)(sm + 4608);    // row-major (c x k), ld=64
    float* scr = (float*)sm;                            // epilogue: [128][68] fp32

    const int which = blockIdx.y;
    const float* x  = which ? x2 : x1;
    const float* Wt = which ? g_Wkt : g_Wqt;
    const float* bv = which ? g_bk : g_bq;
    __nv_bfloat16* out = which ? Ko : Qo;

    const int n0 = blockIdx.x * 128;
    const float* xb = x + (size_t)b * CH * NPIX;
    const int tid = threadIdx.x, w = tid >> 5;
    const int wm = w >> 1, wk = w & 1;

    wmma::fragment<wmma::accumulator, 16, 16, 16, float> acc[2][2];
    #pragma unroll
    for (int mi = 0; mi < 2; ++mi)
        #pragma unroll
        for (int nj = 0; nj < 2; ++nj) wmma::fill_fragment(acc[mi][nj], 0.0f);

    for (int c0 = 0; c0 < CH; c0 += 16) {
        #pragma unroll
        for (int p = 0; p < 8; ++p) {
            int idx = tid + p * 256;
            int cc = idx >> 7, nn = idx & 127;
            As[cc * PJ_LDA + nn] =
                __float2bfloat16(xb[(size_t)(c0 + cc) * NPIX + n0 + nn]);
        }
        #pragma unroll
        for (int p = 0; p < 4; ++p) {
            int idx = tid + p * 256;
            int cc = idx >> 6, k = idx & 63;
            Bs[cc * 64 + k] = __float2bfloat16(Wt[(size_t)(c0 + cc) * CKDIM + k]);
        }
        __syncthreads();
        wmma::fragment<wmma::matrix_a, 16, 16, 16, __nv_bfloat16, wmma::col_major> af[2];
        wmma::fragment<wmma::matrix_b, 16, 16, 16, __nv_bfloat16, wmma::row_major> bf[2];
        #pragma unroll
        for (int mi = 0; mi < 2; ++mi)
            wmma::load_matrix_sync(af[mi], As + wm * 32 + mi * 16, PJ_LDA);
        #pragma unroll
        for (int nj = 0; nj < 2; ++nj)
            wmma::load_matrix_sync(bf[nj], Bs + wk * 32 + nj * 16, 64);
        #pragma unroll
        for (int mi = 0; mi < 2; ++mi)
            #pragma unroll
            for (int nj = 0; nj < 2; ++nj)
                wmma::mma_sync(acc[mi][nj], af[mi], bf[nj], acc[mi][nj]);
        __syncthreads();
    }

    #pragma unroll
    for (int mi = 0; mi < 2; ++mi)
        #pragma unroll
        for (int nj = 0; nj < 2; ++nj)
            wmma::store_matrix_sync(scr + (wm * 32 + mi * 16) * 68 + wk * 32 + nj * 16,
                                    acc[mi][nj], 68, wmma::mem_row_major);
    __syncthreads();
    const int n = tid >> 1;
    const int ks = (tid & 1) * 32;
    __nv_bfloat16* orow = out + ((size_t)b * NPIX + n0 + n) * CKDIM + ks;
    #pragma unroll
    for (int j = 0; j < 8; ++j) {
        float4 v = *(float4*)&scr[n * 68 + ks + j * 4];
        const float* bp = bv + ks + j * 4;
        __nv_bfloat162 lo = __floats2bfloat162_rn(v.x + bp[0], v.y + bp[1]);
        __nv_bfloat162 hi = __floats2bfloat162_rn(v.z + bp[2], v.w + bp[3]);
        uint2 u;
        u.x = *(uint32_t*)&lo;
        u.y = *(uint32_t*)&hi;
        *(uint2*)&orow[j * 4] = u;
    }
}

// ---------------- kernel 1b: V projection via wmma --------------------------
#define PJV_SMEM (128 * 132 * 4 + 128)   // 67712
__global__ __launch_bounds__(256) void projv_kernel(const float* __restrict__ x,
                                                    const float* __restrict__ bd,
                                                    __nv_bfloat16* __restrict__ vh) {
    extern __shared__ char dyn[];
    __nv_bfloat16* As = (__nv_bfloat16*)dyn;            // col-major (n x c), ld=PJ_LDA
    __nv_bfloat16* Bs = (__nv_bfloat16*)(dyn + 4608);   // row-major (c x d), ld=128
    float* scr = (float*)dyn;                           // epilogue: col-major [d][132n]

    const int b  = blockIdx.z;
    const int n0 = blockIdx.x * 128;
    const int d0 = blockIdx.y * 128;
    const float* xb = x + (size_t)b * CH * NPIX;
    const int tid = threadIdx.x, w = tid >> 5;
    const int wm = w >> 1, wd = w & 1;

    wmma::fragment<wmma::accumulator, 16, 16, 16, float> acc[2][4];
    #pragma unroll
    for (int mi = 0; mi < 2; ++mi)
        #pragma unroll
        for (int nj = 0; nj < 4; ++nj) wmma::fill_fragment(acc[mi][nj], 0.0f);

    for (int c0 = 0; c0 < CH; c0 += 16) {
        #pragma unroll
        for (int p = 0; p < 8; ++p) {
            int idx = tid + p * 256;
            int cc = idx >> 7, nn = idx & 127;
            As[cc * PJ_LDA + nn] =
                __float2bfloat16(xb[(size_t)(c0 + cc) * NPIX + n0 + nn]);
        }
        #pragma unroll
        for (int p = 0; p < 8; ++p) {
            int idx = tid + p * 256;
            int cc = idx >> 7, dd = idx & 127;
            Bs[cc * 128 + dd] = __float2bfloat16(g_Wdt[(size_t)(c0 + cc) * CH + d0 + dd]);
        }
        __syncthreads();
        wmma::fragment<wmma::matrix_a, 16, 16, 16, __nv_bfloat16, wmma::col_major> af[2];
        #pragma unroll
        for (int mi = 0; mi < 2; ++mi)
            wmma::load_matrix_sync(af[mi], As + wm * 32 + mi * 16, PJ_LDA);
        #pragma unroll
        for (int nj = 0; nj < 4; ++nj) {
            wmma::fragment<wmma::matrix_b, 16, 16, 16, __nv_bfloat16, wmma::row_major> bf;
            wmma::load_matrix_sync(bf, Bs + wd * 64 + nj * 16, 128);
            #pragma unroll
            for (int mi = 0; mi < 2; ++mi)
                wmma::mma_sync(acc[mi][nj], af[mi], bf, acc[mi][nj]);
        }
        __syncthreads();
    }

    #pragma unroll
    for (int mi = 0; mi < 2; ++mi)
        #pragma unroll
        for (int nj = 0; nj < 4; ++nj)
            wmma::store_matrix_sync(scr + (wd * 64 + nj * 16) * 132 + wm * 32 + mi * 16,
                                    acc[mi][nj], 132, wmma::mem_col_major);
    __syncthreads();
    #pragma unroll
    for (int ds = 0; ds < 16; ++ds) {
        int dcol = (tid >> 5) + ds * 8;
        int n4   = (tid & 31) * 4;
        float bdv = bd[d0 + dcol];
        float4 v = *(float4*)&scr[dcol * 132 + n4];
        __nv_bfloat162 lo = __floats2bfloat162_rn(v.x + bdv, v.y + bdv);
        __nv_bfloat162 hi = __floats2bfloat162_rn(v.z + bdv, v.w + bdv);
        uint2 u;
        u.x = *(uint32_t*)&lo;
        u.y = *(uint32_t*)&hi;
        *(uint2*)&vh[((size_t)b * CH + d0 + dcol) * NPIX + n0 + n4] = u;
    }
}

// ---------------- kernel 2: QK^T -> fp16 S + row exp-sums (Z) ---------------
#define QK_OFF_K   18432
#define QK_OFF_SCR 36864
#define QK_SMEM    (36864 + 8 * 16 * 68 * 4)   // 71680
__global__ __launch_bounds__(256) void qk_wmma_kernel(const __nv_bfloat16* __restrict__ Qb,
                                                      const __nv_bfloat16* __restrict__ Kb,
                                                      __half* __restrict__ S, int b) {
    extern __shared__ char dyn[];
    __nv_bfloat16* Qs = (__nv_bfloat16*)(dyn);
    __nv_bfloat16* Ks = (__nv_bfloat16*)(dyn + QK_OFF_K);
    const int tid = threadIdx.x, w = tid >> 5, lane = tid & 31;
    float* scr = (float*)(dyn + QK_OFF_SCR) + w * (16 * 68);

    const int i0 = blockIdx.y * 128;
    const int j0 = blockIdx.x * 128;

    const uint4* gQ = (const uint4*)(Qb + ((size_t)b * NPIX + i0) * CKDIM);
    const uint4* gK = (const uint4*)(Kb + ((size_t)b * NPIX + j0) * CKDIM);
    #pragma unroll
    for (int p = 0; p < 4; ++p) {
        int idx = tid + p * 256;
        int row = idx >> 3, c8 = idx & 7;
        *(uint4*)&Qs[row * LDT + c8 * 8] = gQ[idx];
        *(uint4*)&Ks[row * LDT + c8 * 8] = gK[idx];
    }
    __syncthreads();

    const int wm = w >> 1, wc = w & 1;
    wmma::fragment<wmma::accumulator, 16, 16, 16, float> acc[2][4];
    #pragma unroll
    for (int mi = 0; mi < 2; ++mi)
        #pragma unroll
        for (int nj = 0; nj < 4; ++nj) wmma::fill_fragment(acc[mi][nj], 0.0f);

    #pragma unroll
    for (int kk = 0; kk < 64; kk += 16) {
        wmma::fragment<wmma::matrix_a, 16, 16, 16, __nv_bfloat16, wmma::row_major> af[2];
        wmma::load_matrix_sync(af[0], Qs + (wm * 32 +  0) * LDT + kk, LDT);
        wmma::load_matrix_sync(af[1], Qs + (wm * 32 + 16) * LDT + kk, LDT);
        #pragma unroll
        for (int nj = 0; nj < 4; ++nj) {
            wmma::fragment<wmma::matrix_b, 16, 16, 16, __nv_bfloat16, wmma::col_major> bf;
            wmma::load_matrix_sync(bf, Ks + (wc * 64 + nj * 16) * LDT + kk, LDT);
            wmma::mma_sync(acc[0][nj], af[0], bf, acc[0][nj]);
            wmma::mma_sync(acc[1][nj], af[1], bf, acc[1][nj]);
        }
    }

    float* Zp = g_Zrow + (size_t)b * NPIX;
    #pragma unroll
    for (int mi = 0; mi < 2; ++mi) {
        #pragma unroll
        for (int nj = 0; nj < 4; ++nj)
            wmma::store_matrix_sync(scr + nj * 16, acc[mi][nj], 68, wmma::mem_row_major);
        __syncwarp();
        const int irow = i0 + wm * 32 + mi * 16;
        uint32_t* outp = (uint32_t*)(S + ((size_t)b * NPIX + irow) * NPIX + j0 + wc * 64);
        #pragma unroll
        for (int r = 0; r < 16; ++r) {
            float2 v = *(float2*)&scr[r * 68 + lane * 2];
            __half2 h2 = __float22half2_rn(v);
            outp[(size_t)r * (NPIX / 2) + lane] = *(uint32_t*)&h2;
            // partial row sum of exp(s) for softmax Z (no max-subtract; |s|<~50)
            float e = __expf(v.x) + __expf(v.y);
            #pragma unroll
            for (int o = 16; o; o >>= 1) e += __shfl_xor_sync(0xffffffffu, e, o);
            if (lane == 0) atomicAdd(Zp + irow + r, e);
        }
        __syncwarp();
    }
}

// ---------------- kernel 3: out = x + base[c] - alpha * sum_n q*V -----------
// A-operand built on the fly from S: p = exp(s)*invZ[m]; q = 0.5*tanh(p/2)
#define PVA_BUF   (128 * LDT * 2)          // 18432 per A buffer (x2)
#define PVB_STAGE (256 * LDT * 2)          // 36864 per V stage (x3)
#define PV_SMEM   (2 * PVA_BUF + 3 * PVB_STAGE + 256)   // 147712
#define LDE 260
__global__ __launch_bounds__(256) void pv_wmma_kernel(const __half* __restrict__ S,
                                                      const __nv_bfloat16* __restrict__ VH,
                                                      const float* __restrict__ xres,
                                                      const float* __restrict__ alpha,
                                                      float* __restrict__ out, int b) {
    extern __shared__ char dyn[];
    const int tid = threadIdx.x, w = tid >> 5;
    const int m0 = blockIdx.x * 128;

    uint32_t dynb = smem_u32(dyn);
    uint32_t base = (dynb + 255u) & ~255u;
    char* sb = dyn + (base - dynb);
    const uint32_t sbase = base;
    __nv_bfloat16* Abuf = (__nv_bfloat16*)sb;           // 2 x (128 x LDT)
    const uint32_t Bbase = sbase + 2 * PVA_BUF;

    // loader mapping: each thread owns one m-row, half the 64-col tile
    const int arow = tid >> 1;
    const int acol = (tid & 1) * 32;
    const float invZ = 1.0f / g_Zrow[(size_t)b * NPIX + m0 + arow];
    const __half* Srow = S + ((size_t)b * NPIX + m0 + arow) * (size_t)NPIX + acol;
    const __nv_bfloat16* pb = VH + (size_t)b * CH * NPIX;

    uint4 areg[4];
    auto loadA = [&](int t) {
        const uint4* p = (const uint4*)(Srow + (size_t)t * 64);
        #pragma unroll
        for (int i = 0; i < 4; ++i) areg[i] = p[i];
    };
    auto transformA = [&](int t) {
        __nv_bfloat16* dst = Abuf + (size_t)(t & 1) * (128 * LDT) + arow * LDT + acol;
        #pragma unroll
        for (int i = 0; i < 4; ++i) {
            uint32_t u[4] = {areg[i].x, areg[i].y, areg[i].z, areg[i].w};
            uint4 ou;
            uint32_t* op = (uint32_t*)&ou;
            #pragma unroll
            for (int j = 0; j < 4; ++j) {
                __half2 hh = *(__half2*)&u[j];
                float2 f = __half22float2(hh);
                float q0 = 0.5f * tanh_fast(0.5f * (__expf(f.x) * invZ));
                float q1 = 0.5f * tanh_fast(0.5f * (__expf(f.y) * invZ));
                __nv_bfloat162 bb = __floats2bfloat162_rn(q0, q1);
                op[j] = *(uint32_t*)&bb;
            }
            *(uint4*)(dst + i * 8) = ou;
        }
    };
    auto issueB = [&](int t) {
        const uint32_t dB = Bbase + (uint32_t)(t % 3) * PVB_STAGE;
        const int n0 = t << 6;
        #pragma unroll
        for (int p = 0; p < 8; ++p) {           // V: 256 rows x 64 bf16
            int idx = tid + p * 256;
            int row = idx >> 3, c8 = idx & 7;
            cpa16(dB + (uint32_t)(row * LDT + c8 * 8) * 2,
                  pb + (size_t)row * NPIX + n0 + c8 * 8);
        }
        cpa_commit();
    };

    const int wm = w >> 2;    // 0..1
    const int wc = w & 3;     // 0..3
    wmma::fragment<wmma::accumulator, 16, 16, 16, float> acc[4][4];
    #pragma unroll
    for (int mi = 0; mi < 4; ++mi)
        #pragma unroll
        for (int nj = 0; nj < 4; ++nj) wmma::fill_fragment(acc[mi][nj], 0.0f);

    loadA(0);
    transformA(0);
    issueB(0);
    issueB(1);

    for (int t = 0; t < 64; ++t) {
        if (t + 1 < 64) loadA(t + 1);          // LDGs fly under this tile's MMAs
        if (t < 63) cpa_wait<1>(); else cpa_wait<0>();
        __syncthreads();                       // A(t) + B(t) visible

        const __nv_bfloat16* cA = Abuf + (size_t)(t & 1) * (128 * LDT);
        const __nv_bfloat16* cB = (const __nv_bfloat16*)(sb + 2 * PVA_BUF + (size_t)(t % 3) * PVB_STAGE);
        #pragma unroll
        for (int kk = 0; kk < 64; kk += 16) {
            wmma::fragment<wmma::matrix_a, 16, 16, 16, __nv_bfloat16, wmma::row_major> af[4];
            #pragma unroll
            for (int mi = 0; mi < 4; ++mi)
                wmma::load_matrix_sync(af[mi], cA + (wm * 64 + mi * 16) * LDT + kk, LDT);
            #pragma unroll
            for (int nj = 0; nj < 4; ++nj) {
                wmma::fragment<wmma::matrix_b, 16, 16, 16, __nv_bfloat16, wmma::col_major> bf;
                wmma::load_matrix_sync(bf, cB + (wc * 64 + nj * 16) * LDT + kk, LDT);
                #pragma unroll
                for (int mi = 0; mi < 4; ++mi)
                    wmma::mma_sync(acc[mi][nj], af[mi], bf, acc[mi][nj]);
            }
        }

        if (t + 1 < 64) transformA(t + 1);     // writes other A buffer
        if (t + 2 < 64) issueB(t + 2);
    }

    // epilogue: stage acc in smem, out = x + base[c] - alpha*acc
    __syncthreads();
    float* Sep = (float*)sb;                   // 128 * LDE * 4 = 133,120 B
    #pragma unroll
    for (int mi = 0; mi < 4; ++mi)
        #pragma unroll
        for (int nj = 0; nj < 4; ++nj)
            wmma::store_matrix_sync(Sep + (wm * 64 + mi * 16) * LDE + wc * 64 + nj * 16,
                                    acc[mi][nj], LDE, wmma::mem_row_major);
    __syncthreads();

    const float al = alpha[0];
    const int ml = tid & 127;
    const int ch = tid >> 7;                   // 0..1
    #pragma unroll 4
    for (int c2 = 0; c2 < 128; ++c2) {
        int c = ch * 128 + c2;
        size_t o = ((size_t)b * CH + c) * NPIX + m0 + ml;
        out[o] = xres[o] + g_base[b * CH + c] - al * Sep[ml * LDE + c];
    }
}

// ---------------- launch ----------------
extern "C" void kernel_launch(void* const* d_in, const int* in_sizes, int n_in,
                              void* d_out, int out_size) {
    const float* x1    = (const float*)d_in[0];
    const float* x2    = (const float*)d_in[1];
    const float* x     = (const float*)d_in[2];
    const float* gamma = (const float*)d_in[3];
    const float* beta  = (const float*)d_in[4];
    const float* mean  = (const float*)d_in[5];
    const float* var   = (const float*)d_in[6];
    const float* Wb    = (const float*)d_in[7];
    const float* bb    = (const float*)d_in[8];
    const float* Wc    = (const float*)d_in[9];
    const float* bc    = (const float*)d_in[10];
    const float* Wd    = (const float*)d_in[11];
    const float* bd    = (const float*)d_in[12];
    const float* alpha = (const float*)d_in[13];
    float* out = (float*)d_out;

    __nv_bfloat16 *Qp, *Kp, *VHp;
    __half* Sp;
    cudaGetSymbolAddress((void**)&Qp,  g_Qb);
    cudaGetSymbolAddress((void**)&Kp,  g_Kb);
    cudaGetSymbolAddress((void**)&VHp, g_VH);
    cudaGetSymbolAddress((void**)&Sp,  g_S);

    cudaFuncSetAttribute(qk_wmma_kernel, cudaFuncAttributeMaxDynamicSharedMemorySize, QK_SMEM);
    cudaFuncSetAttribute(pv_wmma_kernel, cudaFuncAttributeMaxDynamicSharedMemorySize, PV_SMEM);
    cudaFuncSetAttribute(projv_kernel,  cudaFuncAttributeMaxDynamicSharedMemorySize, PJV_SMEM);

    // fork all side/batch streams from capture root
    cudaEventRecord(g_evRoot, 0);
    cudaStreamWaitEvent(g_s2, g_evRoot, 0);
    for (int b = 0; b < BATCH; ++b) cudaStreamWaitEvent(g_sB[b], g_evRoot, 0);

    // side stream: Wd transpose -> V projection; colsum -> base
    transwd_kernel<<<CH, CH, 0, g_s2>>>(Wd);
    colsum_kernel<<<dim3(CH, BATCH), 256, 0, g_s2>>>(x);
    sumv_kernel<<<BATCH, CH, 0, g_s2>>>(Wd, bd, alpha);
    projv_kernel<<<dim3(NPIX / 128, CH / 128, BATCH), 256, PJV_SMEM, g_s2>>>(x, bd, VHp);
    cudaEventRecord(g_evJ, g_s2);

    // weight prep + Z zeroing on default stream
    prep_kernel<<<1, 256>>>(gamma, beta, mean, var);
    zeroz_kernel<<<BATCH * NPIX / 1024, 1024>>>();
    foldw_kernel<<<dim3(CKDIM, 2), 256>>>(Wb, bb, Wc, bc);
    cudaEventRecord(g_evW, 0);

    // per-batch pipelines: projqk -> qk(+Z) -> pv (att fused into qk/pv)
    for (int b = 0; b < BATCH; ++b) {
        cudaStream_t s = g_sB[b];
        cudaStreamWaitEvent(s, g_evW, 0);
        projqk_kernel<<<dim3(NPIX / 128, 2), 256, 0, s>>>(x1, x2, Qp, Kp, b);
        qk_wmma_kernel<<<dim3(NPIX / 128, NPIX / 128), 256, QK_SMEM, s>>>(Qp, Kp, Sp, b);
        cudaStreamWaitEvent(s, g_evJ, 0);
        pv_wmma_kernel<<<dim3(NPIX / 128), 256, PV_SMEM, s>>>(Sp, VHp, x, alpha, out, b);
        cudaEventRecord(g_evB[b], s);
    }

    // join all batch streams into the capture stream
    for (int b = 0; b < BATCH; ++b) cudaStreamWaitEvent(0, g_evB[b], 0);
}

// round 15
// speedup vs baseline: 1.1570x; 1.1570x over previous
#include <cuda_runtime.h>
#include <cuda_bf16.h>
#include <cuda_fp16.h>
#include <mma.h>
#include <math.h>
#include <stdint.h>

using namespace nvcuda;

#define BATCH 4
#define CH    256
#define CKDIM 64
#define NPIX  4096
#define EPS   1e-5f
#define LDT   72            // bf16 smem tile leading dim (qk/pv)
#define PJ_LDA 136          // projections: col-major A ld (bf16)

#define DINL __device__ __forceinline__

// ---------------- device scratch (static, allocation-free) ----------------
__device__ __align__(16) float g_scale[CH];
__device__ __align__(16) float g_shift[CH];
__device__ __align__(16) float g_sx  [BATCH * CH];
__device__ __align__(16) float g_base[BATCH * CH];                        // alpha*0.5*SumV
__device__ __align__(16) float g_Wqt [CH * CKDIM];                        // BN-folded, [c][k]
__device__ __align__(16) float g_Wkt [CH * CKDIM];
__device__ __align__(16) float g_bq  [CKDIM];
__device__ __align__(16) float g_bk  [CKDIM];
__device__ __align__(16) float g_Wdt [CH * CH];                           // Wd^T, [c][d]
__device__ __align__(16) __nv_bfloat16 g_Qb[BATCH * NPIX * CKDIM];        // [b][i][64]
__device__ __align__(16) __nv_bfloat16 g_Kb[BATCH * NPIX * CKDIM];        // [b][j][64]
__device__ __align__(16) __nv_bfloat16 g_VH[(size_t)BATCH * CH * NPIX];   // [b][c][n]
__device__ __align__(16) __half        g_S [(size_t)BATCH * NPIX * NPIX]; // fp16 scores
__device__ __align__(16) __nv_bfloat16 g_Aq[(size_t)BATCH * NPIX * NPIX]; // q = sig(p)-0.5

// ---------------- streams/events (static init: no device mem alloc) --------
static cudaStream_t g_s2, g_sB[BATCH];
static cudaEvent_t  g_evRoot, g_evW, g_evJ, g_evB[BATCH];
static struct _StrInit {
    _StrInit() {
        cudaStreamCreateWithFlags(&g_s2, cudaStreamNonBlocking);
        cudaEventCreateWithFlags(&g_evRoot, cudaEventDisableTiming);
        cudaEventCreateWithFlags(&g_evW, cudaEventDisableTiming);
        cudaEventCreateWithFlags(&g_evJ, cudaEventDisableTiming);
        for (int b = 0; b < BATCH; ++b) {
            cudaStreamCreateWithFlags(&g_sB[b], cudaStreamNonBlocking);
            cudaEventCreateWithFlags(&g_evB[b], cudaEventDisableTiming);
        }
    }
} g_strInit;

// ---------------- helpers ----------------
DINL uint32_t smem_u32(const void* p) {
    uint32_t a;
    asm("{ .reg .u64 t; cvta.to.shared.u64 t, %1; cvt.u32.u64 %0, t; }"
        : "=r"(a) : "l"(p));
    return a;
}
DINL void cpa16(uint32_t dst, const void* src) {
    asm volatile("cp.async.cg.shared.global [%0], [%1], 16;"
                 :: "r"(dst), "l"(src) : "memory");
}
DINL void cpa_commit() { asm volatile("cp.async.commit_group;" ::: "memory"); }
template<int N> DINL void cpa_wait() {
    asm volatile("cp.async.wait_group %0;" :: "n"(N) : "memory");
}
DINL float tanh_fast(float x) {
    float y;
    asm("tanh.approx.f32 %0, %1;" : "=f"(y) : "f"(x));
    return y;
}

// ---------------- kernel 0: fold BN ----------------
__global__ void prep_kernel(const float* __restrict__ gamma,
                            const float* __restrict__ beta,
                            const float* __restrict__ mean,
                            const float* __restrict__ var) {
    int c = threadIdx.x;
    if (c < CH) {
        float s = gamma[c] * rsqrtf(var[c] + EPS);
        g_scale[c] = s;
        g_shift[c] = beta[c] - mean[c] * s;
    }
}

// ---------------- kernel 0a: fold BN into Wb/Wc, transpose -> [c][k] --------
__global__ void foldw_kernel(const float* __restrict__ Wb,
                             const float* __restrict__ bb,
                             const float* __restrict__ Wc,
                             const float* __restrict__ bc) {
    const int k = blockIdx.x, which = blockIdx.y;
    const float* W  = which ? Wc : Wb;
    const float* bi = which ? bc : bb;
    float* Wt = which ? g_Wkt : g_Wqt;
    float* bo = which ? g_bk  : g_bq;
    const int c = threadIdx.x;
    float w = W[(size_t)k * CH + c];
    Wt[c * CKDIM + k] = w * g_scale[c];
    float sh = w * g_shift[c];
    #pragma unroll
    for (int o = 16; o; o >>= 1) sh += __shfl_xor_sync(0xffffffffu, sh, o);
    __shared__ float red[8];
    if ((c & 31) == 0) red[c >> 5] = sh;
    __syncthreads();
    if (c == 0) {
        float tot = 0.f;
        #pragma unroll
        for (int w8 = 0; w8 < 8; ++w8) tot += red[w8];
        bo[k] = bi[k] + tot;
    }
}

// ---------------- kernel 0e: transpose Wd -> [c][d] -------------------------
__global__ void transwd_kernel(const float* __restrict__ Wd) {
    const int d = blockIdx.x, c = threadIdx.x;
    g_Wdt[(size_t)c * CH + d] = Wd[(size_t)d * CH + c];
}

// ---------------- kernel 0b: column sums of x -> sx[b][c] -------------------
__global__ void colsum_kernel(const float* __restrict__ x) {
    const int c = blockIdx.x, b = blockIdx.y;
    const float* row = x + ((size_t)b * CH + c) * NPIX;
    const int t = threadIdx.x;
    float s = 0.f;
    #pragma unroll
    for (int q = 0; q < 16; ++q) s += row[t + q * 256];
    #pragma unroll
    for (int o = 16; o; o >>= 1) s += __shfl_xor_sync(0xffffffffu, s, o);
    __shared__ float ws[8];
    if ((t & 31) == 0) ws[t >> 5] = s;
    __syncthreads();
    if (t == 0) {
        float tot = 0.f;
        #pragma unroll
        for (int w = 0; w < 8; ++w) tot += ws[w];
        g_sx[b * CH + c] = tot;
    }
}

// ---------------- kernel 0c: base[b][c] = alpha*0.5*(Wd[c,:]·sx[b,:] + N*bd) -
__global__ void sumv_kernel(const float* __restrict__ Wd,
                            const float* __restrict__ bd,
                            const float* __restrict__ alpha) {
    const int b = blockIdx.x;
    const int c = threadIdx.x;
    __shared__ float sxs[CH];
    sxs[c] = g_sx[b * CH + c];
    __syncthreads();
    float dot = 0.f;
    const float* wr = Wd + (size_t)c * CH;
    #pragma unroll 8
    for (int k = 0; k < CH; ++k) dot += wr[k] * sxs[k];
    g_base[b * CH + c] = alpha[0] * 0.5f * (dot + (float)NPIX * bd[c]);
}

// ---------------- kernel 1a: Q & K projections via wmma (per batch) ---------
__global__ __launch_bounds__(256) void projqk_kernel(const float* __restrict__ x1,
                                                     const float* __restrict__ x2,
                                                     __nv_bfloat16* __restrict__ Qo,
                                                     __nv_bfloat16* __restrict__ Ko,
                                                     int b) {
    __shared__ __align__(16) char sm[35840];
    __nv_bfloat16* As = (__nv_bfloat16*)sm;             // col-major (n x c), ld=PJ_LDA
    __nv_bfloat16* Bs = (__nv_bfloat16*)(sm + 4608);    // row-major (c x k), ld=64
    float* scr = (float*)sm;                            // epilogue: [128][68] fp32

    const int which = blockIdx.y;
    const float* x  = which ? x2 : x1;
    const float* Wt = which ? g_Wkt : g_Wqt;
    const float* bv = which ? g_bk : g_bq;
    __nv_bfloat16* out = which ? Ko : Qo;

    const int n0 = blockIdx.x * 128;
    const float* xb = x + (size_t)b * CH * NPIX;
    const int tid = threadIdx.x, w = tid >> 5;
    const int wm = w >> 1, wk = w & 1;

    wmma::fragment<wmma::accumulator, 16, 16, 16, float> acc[2][2];
    #pragma unroll
    for (int mi = 0; mi < 2; ++mi)
        #pragma unroll
        for (int nj = 0; nj < 2; ++nj) wmma::fill_fragment(acc[mi][nj], 0.0f);

    for (int c0 = 0; c0 < CH; c0 += 16) {
        #pragma unroll
        for (int p = 0; p < 8; ++p) {
            int idx = tid + p * 256;
            int cc = idx >> 7, nn = idx & 127;
            As[cc * PJ_LDA + nn] =
                __float2bfloat16(xb[(size_t)(c0 + cc) * NPIX + n0 + nn]);
        }
        #pragma unroll
        for (int p = 0; p < 4; ++p) {
            int idx = tid + p * 256;
            int cc = idx >> 6, k = idx & 63;
            Bs[cc * 64 + k] = __float2bfloat16(Wt[(size_t)(c0 + cc) * CKDIM + k]);
        }
        __syncthreads();
        wmma::fragment<wmma::matrix_a, 16, 16, 16, __nv_bfloat16, wmma::col_major> af[2];
        wmma::fragment<wmma::matrix_b, 16, 16, 16, __nv_bfloat16, wmma::row_major> bf[2];
        #pragma unroll
        for (int mi = 0; mi < 2; ++mi)
            wmma::load_matrix_sync(af[mi], As + wm * 32 + mi * 16, PJ_LDA);
        #pragma unroll
        for (int nj = 0; nj < 2; ++nj)
            wmma::load_matrix_sync(bf[nj], Bs + wk * 32 + nj * 16, 64);
        #pragma unroll
        for (int mi = 0; mi < 2; ++mi)
            #pragma unroll
            for (int nj = 0; nj < 2; ++nj)
                wmma::mma_sync(acc[mi][nj], af[mi], bf[nj], acc[mi][nj]);
        __syncthreads();
    }

    #pragma unroll
    for (int mi = 0; mi < 2; ++mi)
        #pragma unroll
        for (int nj = 0; nj < 2; ++nj)
            wmma::store_matrix_sync(scr + (wm * 32 + mi * 16) * 68 + wk * 32 + nj * 16,
                                    acc[mi][nj], 68, wmma::mem_row_major);
    __syncthreads();
    const int n = tid >> 1;
    const int ks = (tid & 1) * 32;
    __nv_bfloat16* orow = out + ((size_t)b * NPIX + n0 + n) * CKDIM + ks;
    #pragma unroll
    for (int j = 0; j < 8; ++j) {
        float4 v = *(float4*)&scr[n * 68 + ks + j * 4];
        const float* bp = bv + ks + j * 4;
        __nv_bfloat162 lo = __floats2bfloat162_rn(v.x + bp[0], v.y + bp[1]);
        __nv_bfloat162 hi = __floats2bfloat162_rn(v.z + bp[2], v.w + bp[3]);
        uint2 u;
        u.x = *(uint32_t*)&lo;
        u.y = *(uint32_t*)&hi;
        *(uint2*)&orow[j * 4] = u;
    }
}

// ---------------- kernel 1b: V projection via wmma --------------------------
#define PJV_SMEM (128 * 132 * 4 + 128)   // 67712
__global__ __launch_bounds__(256) void projv_kernel(const float* __restrict__ x,
                                                    const float* __restrict__ bd,
                                                    __nv_bfloat16* __restrict__ vh) {
    extern __shared__ char dyn[];
    __nv_bfloat16* As = (__nv_bfloat16*)dyn;            // col-major (n x c), ld=PJ_LDA
    __nv_bfloat16* Bs = (__nv_bfloat16*)(dyn + 4608);   // row-major (c x d), ld=128
    float* scr = (float*)dyn;                           // epilogue: col-major [d][132n]

    const int b  = blockIdx.z;
    const int n0 = blockIdx.x * 128;
    const int d0 = blockIdx.y * 128;
    const float* xb = x + (size_t)b * CH * NPIX;
    const int tid = threadIdx.x, w = tid >> 5;
    const int wm = w >> 1, wd = w & 1;

    wmma::fragment<wmma::accumulator, 16, 16, 16, float> acc[2][4];
    #pragma unroll
    for (int mi = 0; mi < 2; ++mi)
        #pragma unroll
        for (int nj = 0; nj < 4; ++nj) wmma::fill_fragment(acc[mi][nj], 0.0f);

    for (int c0 = 0; c0 < CH; c0 += 16) {
        #pragma unroll
        for (int p = 0; p < 8; ++p) {
            int idx = tid + p * 256;
            int cc = idx >> 7, nn = idx & 127;
            As[cc * PJ_LDA + nn] =
                __float2bfloat16(xb[(size_t)(c0 + cc) * NPIX + n0 + nn]);
        }
        #pragma unroll
        for (int p = 0; p < 8; ++p) {
            int idx = tid + p * 256;
            int cc = idx >> 7, dd = idx & 127;
            Bs[cc * 128 + dd] = __float2bfloat16(g_Wdt[(size_t)(c0 + cc) * CH + d0 + dd]);
        }
        __syncthreads();
        wmma::fragment<wmma::matrix_a, 16, 16, 16, __nv_bfloat16, wmma::col_major> af[2];
        #pragma unroll
        for (int mi = 0; mi < 2; ++mi)
            wmma::load_matrix_sync(af[mi], As + wm * 32 + mi * 16, PJ_LDA);
        #pragma unroll
        for (int nj = 0; nj < 4; ++nj) {
            wmma::fragment<wmma::matrix_b, 16, 16, 16, __nv_bfloat16, wmma::row_major> bf;
            wmma::load_matrix_sync(bf, Bs + wd * 64 + nj * 16, 128);
            #pragma unroll
            for (int mi = 0; mi < 2; ++mi)
                wmma::mma_sync(acc[mi][nj], af[mi], bf, acc[mi][nj]);
        }
        __syncthreads();
    }

    #pragma unroll
    for (int mi = 0; mi < 2; ++mi)
        #pragma unroll
        for (int nj = 0; nj < 4; ++nj)
            wmma::store_matrix_sync(scr + (wd * 64 + nj * 16) * 132 + wm * 32 + mi * 16,
                                    acc[mi][nj], 132, wmma::mem_col_major);
    __syncthreads();
    #pragma unroll
    for (int ds = 0; ds < 16; ++ds) {
        int dcol = (tid >> 5) + ds * 8;
        int n4   = (tid & 31) * 4;
        float bdv = bd[d0 + dcol];
        float4 v = *(float4*)&scr[dcol * 132 + n4];
        __nv_bfloat162 lo = __floats2bfloat162_rn(v.x + bdv, v.y + bdv);
        __nv_bfloat162 hi = __floats2bfloat162_rn(v.z + bdv, v.w + bdv);
        uint2 u;
        u.x = *(uint32_t*)&lo;
        u.y = *(uint32_t*)&hi;
        *(uint2*)&vh[((size_t)b * CH + d0 + dcol) * NPIX + n0 + n4] = u;
    }
}

// ---------------- kernel 2: scores = Q @ K^T via wmma bf16 -> fp16 S --------
#define QK_OFF_K   18432
#define QK_OFF_SCR 36864
#define QK_SMEM    (36864 + 8 * 16 * 68 * 4)   // 71680
__global__ __launch_bounds__(256) void qk_wmma_kernel(const __nv_bfloat16* __restrict__ Qb,
                                                      const __nv_bfloat16* __restrict__ Kb,
                                                      __half* __restrict__ S, int b) {
    extern __shared__ char dyn[];
    __nv_bfloat16* Qs = (__nv_bfloat16*)(dyn);
    __nv_bfloat16* Ks = (__nv_bfloat16*)(dyn + QK_OFF_K);
    const int tid = threadIdx.x, w = tid >> 5, lane = tid & 31;
    float* scr = (float*)(dyn + QK_OFF_SCR) + w * (16 * 68);

    const int i0 = blockIdx.y * 128;
    const int j0 = blockIdx.x * 128;

    const uint4* gQ = (const uint4*)(Qb + ((size_t)b * NPIX + i0) * CKDIM);
    const uint4* gK = (const uint4*)(Kb + ((size_t)b * NPIX + j0) * CKDIM);
    #pragma unroll
    for (int p = 0; p < 4; ++p) {
        int idx = tid + p * 256;
        int row = idx >> 3, c8 = idx & 7;
        *(uint4*)&Qs[row * LDT + c8 * 8] = gQ[idx];
        *(uint4*)&Ks[row * LDT + c8 * 8] = gK[idx];
    }
    __syncthreads();

    const int wm = w >> 1, wc = w & 1;
    wmma::fragment<wmma::accumulator, 16, 16, 16, float> acc[2][4];
    #pragma unroll
    for (int mi = 0; mi < 2; ++mi)
        #pragma unroll
        for (int nj = 0; nj < 4; ++nj) wmma::fill_fragment(acc[mi][nj], 0.0f);

    #pragma unroll
    for (int kk = 0; kk < 64; kk += 16) {
        wmma::fragment<wmma::matrix_a, 16, 16, 16, __nv_bfloat16, wmma::row_major> af[2];
        wmma::load_matrix_sync(af[0], Qs + (wm * 32 +  0) * LDT + kk, LDT);
        wmma::load_matrix_sync(af[1], Qs + (wm * 32 + 16) * LDT + kk, LDT);
        #pragma unroll
        for (int nj = 0; nj < 4; ++nj) {
            wmma::fragment<wmma::matrix_b, 16, 16, 16, __nv_bfloat16, wmma::col_major> bf;
            wmma::load_matrix_sync(bf, Ks + (wc * 64 + nj * 16) * LDT + kk, LDT);
            wmma::mma_sync(acc[0][nj], af[0], bf, acc[0][nj]);
            wmma::mma_sync(acc[1][nj], af[1], bf, acc[1][nj]);
        }
    }

    #pragma unroll
    for (int mi = 0; mi < 2; ++mi) {
        #pragma unroll
        for (int nj = 0; nj < 4; ++nj)
            wmma::store_matrix_sync(scr + nj * 16, acc[mi][nj], 68, wmma::mem_row_major);
        __syncwarp();
        const int irow = i0 + wm * 32 + mi * 16;
        uint32_t* outp = (uint32_t*)(S + ((size_t)b * NPIX + irow) * NPIX + j0 + wc * 64);
        #pragma unroll
        for (int r = 0; r < 16; ++r) {
            float2 v = *(float2*)&scr[r * 68 + lane * 2];
            __half2 h2 = __float22half2_rn(v);
            outp[(size_t)r * (NPIX / 2) + lane] = *(uint32_t*)&h2;
        }
        __syncwarp();
    }
}

// ---------------- kernel 3: softmax row -> q = 0.5*tanh(p/2) bf16 -----------
__global__ void att_kernel(const __half* __restrict__ S,
                           __nv_bfloat16* __restrict__ Aq, int b) {
    const size_t roff = ((size_t)b * NPIX + blockIdx.x) * (size_t)NPIX;
    const __half2* r2 = (const __half2*)(S + roff);
    __nv_bfloat162* o2 = (__nv_bfloat162*)(Aq + roff);
    const int t = threadIdx.x;
    const int lane = t & 31, wid = t >> 5;
    __shared__ float smax[8];
    __shared__ float ssum[8];

    float v[16];
    float mx = -1e30f;
    #pragma unroll
    for (int q = 0; q < 8; ++q) {
        float2 f = __half22float2(r2[t + q * 256]);
        v[2 * q] = f.x; v[2 * q + 1] = f.y;
        mx = fmaxf(mx, fmaxf(f.x, f.y));
    }
    #pragma unroll
    for (int o = 16; o; o >>= 1) mx = fmaxf(mx, __shfl_xor_sync(0xffffffffu, mx, o));
    if (lane == 0) smax[wid] = mx;
    __syncthreads();
    mx = smax[0];
    #pragma unroll
    for (int w = 1; w < 8; ++w) mx = fmaxf(mx, smax[w]);

    float s = 0.f;
    #pragma unroll
    for (int q = 0; q < 16; ++q) { v[q] = __expf(v[q] - mx); s += v[q]; }
    #pragma unroll
    for (int o = 16; o; o >>= 1) s += __shfl_xor_sync(0xffffffffu, s, o);
    if (lane == 0) ssum[wid] = s;
    __syncthreads();
    float Z = 0.f;
    #pragma unroll
    for (int w = 0; w < 8; ++w) Z += ssum[w];
    float inv = 1.0f / Z;

    #pragma unroll
    for (int q = 0; q < 8; ++q) {
        float q0 = 0.5f * tanh_fast(0.5f * (v[2 * q] * inv));
        float q1 = 0.5f * tanh_fast(0.5f * (v[2 * q + 1] * inv));
        o2[t + q * 256] = __floats2bfloat162_rn(q0, q1);
    }
}

// ---------------- kernel 4: out[b,c,m] = x + base[c] - alpha * sum_n q*V ----
// bf16 GEMM: CTA 64m x 256c, 8 warps = 2(m) x 4(c); 2-stage, 2 CTAs/SM
#define PVM 64
#define PV_STAGE_B ((PVM * LDT + 256 * LDT) * 2)   // 46080 bytes per stage
#define PV_SMEM    (2 * PV_STAGE_B + 256)          // 92416
#define LDE 260
__global__ __launch_bounds__(256, 2) void pv_wmma_kernel(const __nv_bfloat16* __restrict__ Aq,
                                                         const __nv_bfloat16* __restrict__ VH,
                                                         const float* __restrict__ xres,
                                                         const float* __restrict__ alpha,
                                                         float* __restrict__ out, int b) {
    extern __shared__ char dyn[];
    const int tid = threadIdx.x, w = tid >> 5;
    const int m0 = blockIdx.x * PVM;

    uint32_t dynb = smem_u32(dyn);
    uint32_t base = (dynb + 255u) & ~255u;
    char* sb = dyn + (base - dynb);
    const uint32_t sbase = base;

    const __nv_bfloat16* pa = Aq + ((size_t)b * NPIX + m0) * (size_t)NPIX;
    const __nv_bfloat16* pb = VH + (size_t)b * CH * NPIX;

    auto issue_stage = [&](int t) {
        const int s = t & 1;
        const uint32_t dA = sbase + (uint32_t)s * PV_STAGE_B;
        const uint32_t dB = dA + PVM * LDT * 2;
        const int n0 = t << 6;
        #pragma unroll
        for (int p = 0; p < 2; ++p) {           // A: 64 rows x 64 bf16
            int idx = tid + p * 256;
            int row = idx >> 3, c8 = idx & 7;
            cpa16(dA + (uint32_t)(row * LDT + c8 * 8) * 2,
                  pa + (size_t)row * NPIX + n0 + c8 * 8);
        }
        #pragma unroll
        for (int p = 0; p < 8; ++p) {           // B: 256 rows x 64 bf16
            int idx = tid + p * 256;
            int row = idx >> 3, c8 = idx & 7;
            cpa16(dB + (uint32_t)(row * LDT + c8 * 8) * 2,
                  pb + (size_t)row * NPIX + n0 + c8 * 8);
        }
        cpa_commit();
    };

    const int wm = w >> 2;    // 0..1 (32 m each)
    const int wc = w & 3;     // 0..3 (64 c each)
    wmma::fragment<wmma::accumulator, 16, 16, 16, float> acc[2][4];
    #pragma unroll
    for (int mi = 0; mi < 2; ++mi)
        #pragma unroll
        for (int nj = 0; nj < 4; ++nj) wmma::fill_fragment(acc[mi][nj], 0.0f);

    issue_stage(0);
    issue_stage(1);

    for (int t = 0; t < 64; ++t) {
        if (t < 63) cpa_wait<1>(); else cpa_wait<0>();
        __syncthreads();

        const __nv_bfloat16* cA = (const __nv_bfloat16*)(sb + (size_t)(t & 1) * PV_STAGE_B);
        const __nv_bfloat16* cB = cA + PVM * LDT;
        #pragma unroll
        for (int kk = 0; kk < 64; kk += 16) {
            wmma::fragment<wmma::matrix_a, 16, 16, 16, __nv_bfloat16, wmma::row_major> af[2];
            #pragma unroll
            for (int mi = 0; mi < 2; ++mi)
                wmma::load_matrix_sync(af[mi], cA + (wm * 32 + mi * 16) * LDT + kk, LDT);
            #pragma unroll
            for (int nj = 0; nj < 4; ++nj) {
                wmma::fragment<wmma::matrix_b, 16, 16, 16, __nv_bfloat16, wmma::col_major> bf;
                wmma::load_matrix_sync(bf, cB + (wc * 64 + nj * 16) * LDT + kk, LDT);
                #pragma unroll
                for (int mi = 0; mi < 2; ++mi)
                    wmma::mma_sync(acc[mi][nj], af[mi], bf, acc[mi][nj]);
            }
        }

        __syncthreads();                 // all reads of buffer (t&1) done
        if (t + 2 < 64) issue_stage(t + 2);   // refill same buffer
    }

    // epilogue: stage acc in smem, out = x + base[c] - alpha*acc
    __syncthreads();
    float* Sep = (float*)sb;                   // 64 * LDE * 4 = 66,560 B
    #pragma unroll
    for (int mi = 0; mi < 2; ++mi)
        #pragma unroll
        for (int nj = 0; nj < 4; ++nj)
            wmma::store_matrix_sync(Sep + (wm * 32 + mi * 16) * LDE + wc * 64 + nj * 16,
                                    acc[mi][nj], LDE, wmma::mem_row_major);
    __syncthreads();

    const float al = alpha[0];
    const int ml = tid & 63;
    const int ch = tid >> 6;                   // 0..3
    #pragma unroll 4
    for (int c2 = 0; c2 < 64; ++c2) {
        int c = ch * 64 + c2;
        size_t o = ((size_t)b * CH + c) * NPIX + m0 + ml;
        out[o] = xres[o] + g_base[b * CH + c] - al * Sep[ml * LDE + c];
    }
}

// ---------------- launch ----------------
extern "C" void kernel_launch(void* const* d_in, const int* in_sizes, int n_in,
                              void* d_out, int out_size) {
    const float* x1    = (const float*)d_in[0];
    const float* x2    = (const float*)d_in[1];
    const float* x     = (const float*)d_in[2];
    const float* gamma = (const float*)d_in[3];
    const float* beta  = (const float*)d_in[4];
    const float* mean  = (const float*)d_in[5];
    const float* var   = (const float*)d_in[6];
    const float* Wb    = (const float*)d_in[7];
    const float* bb    = (const float*)d_in[8];
    const float* Wc    = (const float*)d_in[9];
    const float* bc    = (const float*)d_in[10];
    const float* Wd    = (const float*)d_in[11];
    const float* bd    = (const float*)d_in[12];
    const float* alpha = (const float*)d_in[13];
    float* out = (float*)d_out;

    __nv_bfloat16 *Qp, *Kp, *VHp, *Aqp;
    __half* Sp;
    cudaGetSymbolAddress((void**)&Qp,  g_Qb);
    cudaGetSymbolAddress((void**)&Kp,  g_Kb);
    cudaGetSymbolAddress((void**)&VHp, g_VH);
    cudaGetSymbolAddress((void**)&Sp,  g_S);
    cudaGetSymbolAddress((void**)&Aqp, g_Aq);

    cudaFuncSetAttribute(qk_wmma_kernel, cudaFuncAttributeMaxDynamicSharedMemorySize, QK_SMEM);
    cudaFuncSetAttribute(pv_wmma_kernel, cudaFuncAttributeMaxDynamicSharedMemorySize, PV_SMEM);
    cudaFuncSetAttribute(projv_kernel,  cudaFuncAttributeMaxDynamicSharedMemorySize, PJV_SMEM);

    // fork all side/batch streams from capture root
    cudaEventRecord(g_evRoot, 0);
    cudaStreamWaitEvent(g_s2, g_evRoot, 0);
    for (int b = 0; b < BATCH; ++b) cudaStreamWaitEvent(g_sB[b], g_evRoot, 0);

    // side stream: Wd transpose -> V projection; colsum -> base
    transwd_kernel<<<CH, CH, 0, g_s2>>>(Wd);
    colsum_kernel<<<dim3(CH, BATCH), 256, 0, g_s2>>>(x);
    sumv_kernel<<<BATCH, CH, 0, g_s2>>>(Wd, bd, alpha);
    projv_kernel<<<dim3(NPIX / 128, CH / 128, BATCH), 256, PJV_SMEM, g_s2>>>(x, bd, VHp);
    cudaEventRecord(g_evJ, g_s2);

    // weight prep on default stream
    prep_kernel<<<1, 256>>>(gamma, beta, mean, var);
    foldw_kernel<<<dim3(CKDIM, 2), 256>>>(Wb, bb, Wc, bc);
    cudaEventRecord(g_evW, 0);

    // per-batch pipelines
    for (int b = 0; b < BATCH; ++b) {
        cudaStream_t s = g_sB[b];
        cudaStreamWaitEvent(s, g_evW, 0);
        projqk_kernel<<<dim3(NPIX / 128, 2), 256, 0, s>>>(x1, x2, Qp, Kp, b);
        qk_wmma_kernel<<<dim3(NPIX / 128, NPIX / 128), 256, QK_SMEM, s>>>(Qp, Kp, Sp, b);
        att_kernel<<<NPIX, 256, 0, s>>>(Sp, Aqp, b);
        cudaStreamWaitEvent(s, g_evJ, 0);
        pv_wmma_kernel<<<dim3(NPIX / PVM), 256, PV_SMEM, s>>>(Aqp, VHp, x, alpha, out, b);
        cudaEventRecord(g_evB[b], s);
    }

    // join all batch streams into the capture stream
    for (int b = 0; b < BATCH; ++b) cudaStreamWaitEvent(0, g_evB[b], 0);
}

// round 17
// speedup vs baseline: 1.1841x; 1.0234x over previous
#include <cuda_runtime.h>
#include <cuda_bf16.h>
#include <cuda_fp16.h>
#include <mma.h>
#include <math.h>
#include <stdint.h>

using namespace nvcuda;

#define BATCH 4
#define CH    256
#define CKDIM 64
#define NPIX  4096
#define EPS   1e-5f
#define LDT   72            // bf16 smem tile leading dim (qk/pv)
#define PJ_LDA 136          // projections: col-major A ld (bf16)
#define NHALF 2             // per-batch half-chains

#define DINL __device__ __forceinline__

// ---------------- device scratch (static, allocation-free) ----------------
__device__ __align__(16) float g_scale[CH];
__device__ __align__(16) float g_shift[CH];
__device__ __align__(16) float g_sx  [BATCH * CH];
__device__ __align__(16) float g_base[BATCH * CH];                        // alpha*0.5*SumV
__device__ __align__(16) float g_Wqt [CH * CKDIM];                        // BN-folded, [c][k]
__device__ __align__(16) float g_Wkt [CH * CKDIM];
__device__ __align__(16) float g_bq  [CKDIM];
__device__ __align__(16) float g_bk  [CKDIM];
__device__ __align__(16) float g_Wdt [CH * CH];                           // Wd^T, [c][d]
__device__ __align__(16) __nv_bfloat16 g_Qb[BATCH * NPIX * CKDIM];        // [b][i][64]
__device__ __align__(16) __nv_bfloat16 g_Kb[BATCH * NPIX * CKDIM];        // [b][j][64]
__device__ __align__(16) __nv_bfloat16 g_VH[(size_t)BATCH * CH * NPIX];   // [b][c][n]
__device__ __align__(16) __half        g_S [(size_t)BATCH * NPIX * NPIX]; // fp16 scores
__device__ __align__(16) __nv_bfloat16 g_Aq[(size_t)BATCH * NPIX * NPIX]; // q = sig(p)-0.5

// ---------------- streams/events (static init: no device mem alloc) --------
static cudaStream_t g_s2, g_sH[BATCH * NHALF];
static cudaEvent_t  g_evRoot, g_evW, g_evJ, g_evP[BATCH], g_evH[BATCH * NHALF];
static struct _StrInit {
    _StrInit() {
        cudaStreamCreateWithFlags(&g_s2, cudaStreamNonBlocking);
        cudaEventCreateWithFlags(&g_evRoot, cudaEventDisableTiming);
        cudaEventCreateWithFlags(&g_evW, cudaEventDisableTiming);
        cudaEventCreateWithFlags(&g_evJ, cudaEventDisableTiming);
        for (int b = 0; b < BATCH; ++b)
            cudaEventCreateWithFlags(&g_evP[b], cudaEventDisableTiming);
        for (int i = 0; i < BATCH * NHALF; ++i) {
            cudaStreamCreateWithFlags(&g_sH[i], cudaStreamNonBlocking);
            cudaEventCreateWithFlags(&g_evH[i], cudaEventDisableTiming);
        }
    }
} g_strInit;

// ---------------- helpers ----------------
DINL uint32_t smem_u32(const void* p) {
    uint32_t a;
    asm("{ .reg .u64 t; cvta.to.shared.u64 t, %1; cvt.u32.u64 %0, t; }"
        : "=r"(a) : "l"(p));
    return a;
}
DINL void cpa16(uint32_t dst, const void* src) {
    asm volatile("cp.async.cg.shared.global [%0], [%1], 16;"
                 :: "r"(dst), "l"(src) : "memory");
}
DINL void cpa_commit() { asm volatile("cp.async.commit_group;" ::: "memory"); }
template<int N> DINL void cpa_wait() {
    asm volatile("cp.async.wait_group %0;" :: "n"(N) : "memory");
}
DINL float tanh_fast(float x) {
    float y;
    asm("tanh.approx.f32 %0, %1;" : "=f"(y) : "f"(x));
    return y;
}

// ---------------- kernel 0: fold BN ----------------
__global__ void prep_kernel(const float* __restrict__ gamma,
                            const float* __restrict__ beta,
                            const float* __restrict__ mean,
                            const float* __restrict__ var) {
    int c = threadIdx.x;
    if (c < CH) {
        float s = gamma[c] * rsqrtf(var[c] + EPS);
        g_scale[c] = s;
        g_shift[c] = beta[c] - mean[c] * s;
    }
}

// ---------------- kernel 0a: fold BN into Wb/Wc, transpose -> [c][k] --------
__global__ void foldw_kernel(const float* __restrict__ Wb,
                             const float* __restrict__ bb,
                             const float* __restrict__ Wc,
                             const float* __restrict__ bc) {
    const int k = blockIdx.x, which = blockIdx.y;
    const float* W  = which ? Wc : Wb;
    const float* bi = which ? bc : bb;
    float* Wt = which ? g_Wkt : g_Wqt;
    float* bo = which ? g_bk  : g_bq;
    const int c = threadIdx.x;
    float w = W[(size_t)k * CH + c];
    Wt[c * CKDIM + k] = w * g_scale[c];
    float sh = w * g_shift[c];
    #pragma unroll
    for (int o = 16; o; o >>= 1) sh += __shfl_xor_sync(0xffffffffu, sh, o);
    __shared__ float red[8];
    if ((c & 31) == 0) red[c >> 5] = sh;
    __syncthreads();
    if (c == 0) {
        float tot = 0.f;
        #pragma unroll
        for (int w8 = 0; w8 < 8; ++w8) tot += red[w8];
        bo[k] = bi[k] + tot;
    }
}

// ---------------- kernel 0e: transpose Wd -> [c][d] -------------------------
__global__ void transwd_kernel(const float* __restrict__ Wd) {
    const int d = blockIdx.x, c = threadIdx.x;
    g_Wdt[(size_t)c * CH + d] = Wd[(size_t)d * CH + c];
}

// ---------------- kernel 0b: column sums of x -> sx[b][c] -------------------
__global__ void colsum_kernel(const float* __restrict__ x) {
    const int c = blockIdx.x, b = blockIdx.y;
    const float* row = x + ((size_t)b * CH + c) * NPIX;
    const int t = threadIdx.x;
    float s = 0.f;
    #pragma unroll
    for (int q = 0; q < 16; ++q) s += row[t + q * 256];
    #pragma unroll
    for (int o = 16; o; o >>= 1) s += __shfl_xor_sync(0xffffffffu, s, o);
    __shared__ float ws[8];
    if ((t & 31) == 0) ws[t >> 5] = s;
    __syncthreads();
    if (t == 0) {
        float tot = 0.f;
        #pragma unroll
        for (int w = 0; w < 8; ++w) tot += ws[w];
        g_sx[b * CH + c] = tot;
    }
}

// ---------------- kernel 0c: base[b][c] = alpha*0.5*(Wd[c,:]·sx[b,:] + N*bd) -
__global__ void sumv_kernel(const float* __restrict__ Wd,
                            const float* __restrict__ bd,
                            const float* __restrict__ alpha) {
    const int b = blockIdx.x;
    const int c = threadIdx.x;
    __shared__ float sxs[CH];
    sxs[c] = g_sx[b * CH + c];
    __syncthreads();
    float dot = 0.f;
    const float* wr = Wd + (size_t)c * CH;
    #pragma unroll 8
    for (int k = 0; k < CH; ++k) dot += wr[k] * sxs[k];
    g_base[b * CH + c] = alpha[0] * 0.5f * (dot + (float)NPIX * bd[c]);
}

// ---------------- kernel 1a: Q & K projections via wmma (per batch) ---------
__global__ __launch_bounds__(256) void projqk_kernel(const float* __restrict__ x1,
                                                     const float* __restrict__ x2,
                                                     __nv_bfloat16* __restrict__ Qo,
                                                     __nv_bfloat16* __restrict__ Ko,
                                                     int b) {
    __shared__ __align__(16) char sm[35840];
    __nv_bfloat16* As = (__nv_bfloat16*)sm;             // col-major (n x c), ld=PJ_LDA
    __nv_bfloat16* Bs = (__nv_bfloat16*)(sm + 4608);    // row-major (c x k), ld=64
    float* scr = (float*)sm;                            // epilogue: [128][68] fp32

    const int which = blockIdx.y;
    const float* x  = which ? x2 : x1;
    const float* Wt = which ? g_Wkt : g_Wqt;
    const float* bv = which ? g_bk : g_bq;
    __nv_bfloat16* out = which ? Ko : Qo;

    const int n0 = blockIdx.x * 128;
    const float* xb = x + (size_t)b * CH * NPIX;
    const int tid = threadIdx.x, w = tid >> 5;
    const int wm = w >> 1, wk = w & 1;

    wmma::fragment<wmma::accumulator, 16, 16, 16, float> acc[2][2];
    #pragma unroll
    for (int mi = 0; mi < 2; ++mi)
        #pragma unroll
        for (int nj = 0; nj < 2; ++nj) wmma::fill_fragment(acc[mi][nj], 0.0f);

    for (int c0 = 0; c0 < CH; c0 += 16) {
        #pragma unroll
        for (int p = 0; p < 8; ++p) {
            int idx = tid + p * 256;
            int cc = idx >> 7, nn = idx & 127;
            As[cc * PJ_LDA + nn] =
                __float2bfloat16(xb[(size_t)(c0 + cc) * NPIX + n0 + nn]);
        }
        #pragma unroll
        for (int p = 0; p < 4; ++p) {
            int idx = tid + p * 256;
            int cc = idx >> 6, k = idx & 63;
            Bs[cc * 64 + k] = __float2bfloat16(Wt[(size_t)(c0 + cc) * CKDIM + k]);
        }
        __syncthreads();
        wmma::fragment<wmma::matrix_a, 16, 16, 16, __nv_bfloat16, wmma::col_major> af[2];
        wmma::fragment<wmma::matrix_b, 16, 16, 16, __nv_bfloat16, wmma::row_major> bf[2];
        #pragma unroll
        for (int mi = 0; mi < 2; ++mi)
            wmma::load_matrix_sync(af[mi], As + wm * 32 + mi * 16, PJ_LDA);
        #pragma unroll
        for (int nj = 0; nj < 2; ++nj)
            wmma::load_matrix_sync(bf[nj], Bs + wk * 32 + nj * 16, 64);
        #pragma unroll
        for (int mi = 0; mi < 2; ++mi)
            #pragma unroll
            for (int nj = 0; nj < 2; ++nj)
                wmma::mma_sync(acc[mi][nj], af[mi], bf[nj], acc[mi][nj]);
        __syncthreads();
    }

    #pragma unroll
    for (int mi = 0; mi < 2; ++mi)
        #pragma unroll
        for (int nj = 0; nj < 2; ++nj)
            wmma::store_matrix_sync(scr + (wm * 32 + mi * 16) * 68 + wk * 32 + nj * 16,
                                    acc[mi][nj], 68, wmma::mem_row_major);
    __syncthreads();
    const int n = tid >> 1;
    const int ks = (tid & 1) * 32;
    __nv_bfloat16* orow = out + ((size_t)b * NPIX + n0 + n) * CKDIM + ks;
    #pragma unroll
    for (int j = 0; j < 8; ++j) {
        float4 v = *(float4*)&scr[n * 68 + ks + j * 4];
        const float* bp = bv + ks + j * 4;
        __nv_bfloat162 lo = __floats2bfloat162_rn(v.x + bp[0], v.y + bp[1]);
        __nv_bfloat162 hi = __floats2bfloat162_rn(v.z + bp[2], v.w + bp[3]);
        uint2 u;
        u.x = *(uint32_t*)&lo;
        u.y = *(uint32_t*)&hi;
        *(uint2*)&orow[j * 4] = u;
    }
}

// ---------------- kernel 1b: V projection via wmma --------------------------
#define PJV_SMEM (128 * 132 * 4 + 128)   // 67712
__global__ __launch_bounds__(256) void projv_kernel(const float* __restrict__ x,
                                                    const float* __restrict__ bd,
                                                    __nv_bfloat16* __restrict__ vh) {
    extern __shared__ char dyn[];
    __nv_bfloat16* As = (__nv_bfloat16*)dyn;            // col-major (n x c), ld=PJ_LDA
    __nv_bfloat16* Bs = (__nv_bfloat16*)(dyn + 4608);   // row-major (c x d), ld=128
    float* scr = (float*)dyn;                           // epilogue: col-major [d][132n]

    const int b  = blockIdx.z;
    const int n0 = blockIdx.x * 128;
    const int d0 = blockIdx.y * 128;
    const float* xb = x + (size_t)b * CH * NPIX;
    const int tid = threadIdx.x, w = tid >> 5;
    const int wm = w >> 1, wd = w & 1;

    wmma::fragment<wmma::accumulator, 16, 16, 16, float> acc[2][4];
    #pragma unroll
    for (int mi = 0; mi < 2; ++mi)
        #pragma unroll
        for (int nj = 0; nj < 4; ++nj) wmma::fill_fragment(acc[mi][nj], 0.0f);

    for (int c0 = 0; c0 < CH; c0 += 16) {
        #pragma unroll
        for (int p = 0; p < 8; ++p) {
            int idx = tid + p * 256;
            int cc = idx >> 7, nn = idx & 127;
            As[cc * PJ_LDA + nn] =
                __float2bfloat16(xb[(size_t)(c0 + cc) * NPIX + n0 + nn]);
        }
        #pragma unroll
        for (int p = 0; p < 8; ++p) {
            int idx = tid + p * 256;
            int cc = idx >> 7, dd = idx & 127;
            Bs[cc * 128 + dd] = __float2bfloat16(g_Wdt[(size_t)(c0 + cc) * CH + d0 + dd]);
        }
        __syncthreads();
        wmma::fragment<wmma::matrix_a, 16, 16, 16, __nv_bfloat16, wmma::col_major> af[2];
        #pragma unroll
        for (int mi = 0; mi < 2; ++mi)
            wmma::load_matrix_sync(af[mi], As + wm * 32 + mi * 16, PJ_LDA);
        #pragma unroll
        for (int nj = 0; nj < 4; ++nj) {
            wmma::fragment<wmma::matrix_b, 16, 16, 16, __nv_bfloat16, wmma::row_major> bf;
            wmma::load_matrix_sync(bf, Bs + wd * 64 + nj * 16, 128);
            #pragma unroll
            for (int mi = 0; mi < 2; ++mi)
                wmma::mma_sync(acc[mi][nj], af[mi], bf, acc[mi][nj]);
        }
        __syncthreads();
    }

    #pragma unroll
    for (int mi = 0; mi < 2; ++mi)
        #pragma unroll
        for (int nj = 0; nj < 4; ++nj)
            wmma::store_matrix_sync(scr + (wd * 64 + nj * 16) * 132 + wm * 32 + mi * 16,
                                    acc[mi][nj], 132, wmma::mem_col_major);
    __syncthreads();
    #pragma unroll
    for (int ds = 0; ds < 16; ++ds) {
        int dcol = (tid >> 5) + ds * 8;
        int n4   = (tid & 31) * 4;
        float bdv = bd[d0 + dcol];
        float4 v = *(float4*)&scr[dcol * 132 + n4];
        __nv_bfloat162 lo = __floats2bfloat162_rn(v.x + bdv, v.y + bdv);
        __nv_bfloat162 hi = __floats2bfloat162_rn(v.z + bdv, v.w + bdv);
        uint2 u;
        u.x = *(uint32_t*)&lo;
        u.y = *(uint32_t*)&hi;
        *(uint2*)&vh[((size_t)b * CH + d0 + dcol) * NPIX + n0 + n4] = u;
    }
}

// ---------------- kernel 2: scores = Q @ K^T via wmma bf16 -> fp16 S --------
// grid (32, 16) per half; i0 offset by half
#define QK_OFF_K   18432
#define QK_OFF_SCR 36864
#define QK_SMEM    (36864 + 8 * 16 * 68 * 4)   // 71680
__global__ __launch_bounds__(256) void qk_wmma_kernel(const __nv_bfloat16* __restrict__ Qb,
                                                      const __nv_bfloat16* __restrict__ Kb,
                                                      __half* __restrict__ S,
                                                      int b, int ibase) {
    extern __shared__ char dyn[];
    __nv_bfloat16* Qs = (__nv_bfloat16*)(dyn);
    __nv_bfloat16* Ks = (__nv_bfloat16*)(dyn + QK_OFF_K);
    const int tid = threadIdx.x, w = tid >> 5, lane = tid & 31;
    float* scr = (float*)(dyn + QK_OFF_SCR) + w * (16 * 68);

    const int i0 = (ibase + blockIdx.y) * 128;
    const int j0 = blockIdx.x * 128;

    const uint4* gQ = (const uint4*)(Qb + ((size_t)b * NPIX + i0) * CKDIM);
    const uint4* gK = (const uint4*)(Kb + ((size_t)b * NPIX + j0) * CKDIM);
    #pragma unroll
    for (int p = 0; p < 4; ++p) {
        int idx = tid + p * 256;
        int row = idx >> 3, c8 = idx & 7;
        *(uint4*)&Qs[row * LDT + c8 * 8] = gQ[idx];
        *(uint4*)&Ks[row * LDT + c8 * 8] = gK[idx];
    }
    __syncthreads();

    const int wm = w >> 1, wc = w & 1;
    wmma::fragment<wmma::accumulator, 16, 16, 16, float> acc[2][4];
    #pragma unroll
    for (int mi = 0; mi < 2; ++mi)
        #pragma unroll
        for (int nj = 0; nj < 4; ++nj) wmma::fill_fragment(acc[mi][nj], 0.0f);

    #pragma unroll
    for (int kk = 0; kk < 64; kk += 16) {
        wmma::fragment<wmma::matrix_a, 16, 16, 16, __nv_bfloat16, wmma::row_major> af[2];
        wmma::load_matrix_sync(af[0], Qs + (wm * 32 +  0) * LDT + kk, LDT);
        wmma::load_matrix_sync(af[1], Qs + (wm * 32 + 16) * LDT + kk, LDT);
        #pragma unroll
        for (int nj = 0; nj < 4; ++nj) {
            wmma::fragment<wmma::matrix_b, 16, 16, 16, __nv_bfloat16, wmma::col_major> bf;
            wmma::load_matrix_sync(bf, Ks + (wc * 64 + nj * 16) * LDT + kk, LDT);
            wmma::mma_sync(acc[0][nj], af[0], bf, acc[0][nj]);
            wmma::mma_sync(acc[1][nj], af[1], bf, acc[1][nj]);
        }
    }

    #pragma unroll
    for (int mi = 0; mi < 2; ++mi) {
        #pragma unroll
        for (int nj = 0; nj < 4; ++nj)
            wmma::store_matrix_sync(scr + nj * 16, acc[mi][nj], 68, wmma::mem_row_major);
        __syncwarp();
        const int irow = i0 + wm * 32 + mi * 16;
        uint32_t* outp = (uint32_t*)(S + ((size_t)b * NPIX + irow) * NPIX + j0 + wc * 64);
        #pragma unroll
        for (int r = 0; r < 16; ++r) {
            float2 v = *(float2*)&scr[r * 68 + lane * 2];
            __half2 h2 = __float22half2_rn(v);
            outp[(size_t)r * (NPIX / 2) + lane] = *(uint32_t*)&h2;
        }
        __syncwarp();
    }
}

// ---------------- kernel 3: softmax row -> q = 0.5*tanh(p/2) bf16 -----------
__global__ void att_kernel(const __half* __restrict__ S,
                           __nv_bfloat16* __restrict__ Aq, int b, int rbase) {
    const size_t roff = ((size_t)b * NPIX + rbase + blockIdx.x) * (size_t)NPIX;
    const __half2* r2 = (const __half2*)(S + roff);
    __nv_bfloat162* o2 = (__nv_bfloat162*)(Aq + roff);
    const int t = threadIdx.x;
    const int lane = t & 31, wid = t >> 5;
    __shared__ float smax[8];
    __shared__ float ssum[8];

    float v[16];
    float mx = -1e30f;
    #pragma unroll
    for (int q = 0; q < 8; ++q) {
        float2 f = __half22float2(r2[t + q * 256]);
        v[2 * q] = f.x; v[2 * q + 1] = f.y;
        mx = fmaxf(mx, fmaxf(f.x, f.y));
    }
    #pragma unroll
    for (int o = 16; o; o >>= 1) mx = fmaxf(mx, __shfl_xor_sync(0xffffffffu, mx, o));
    if (lane == 0) smax[wid] = mx;
    __syncthreads();
    mx = smax[0];
    #pragma unroll
    for (int w = 1; w < 8; ++w) mx = fmaxf(mx, smax[w]);

    float s = 0.f;
    #pragma unroll
    for (int q = 0; q < 16; ++q) { v[q] = __expf(v[q] - mx); s += v[q]; }
    #pragma unroll
    for (int o = 16; o; o >>= 1) s += __shfl_xor_sync(0xffffffffu, s, o);
    if (lane == 0) ssum[wid] = s;
    __syncthreads();
    float Z = 0.f;
    #pragma unroll
    for (int w = 0; w < 8; ++w) Z += ssum[w];
    float inv = 1.0f / Z;

    #pragma unroll
    for (int q = 0; q < 8; ++q) {
        float q0 = 0.5f * tanh_fast(0.5f * (v[2 * q] * inv));
        float q1 = 0.5f * tanh_fast(0.5f * (v[2 * q + 1] * inv));
        o2[t + q * 256] = __floats2bfloat162_rn(q0, q1);
    }
}

// ---------------- kernel 4: out[b,c,m] = x + base[c] - alpha * sum_n q*V ----
// bf16 GEMM: CTA 128m x 256c, 8 warps, K=4096 in 64-chunks, 3-stage depth-2
#define PV_STAGE_B ((128 * LDT + 256 * LDT) * 2)   // 55296 bytes per stage
#define PV_SMEM    (3 * PV_STAGE_B + 256)          // 166144
#define LDE 260
__global__ __launch_bounds__(256) void pv_wmma_kernel(const __nv_bfloat16* __restrict__ Aq,
                                                      const __nv_bfloat16* __restrict__ VH,
                                                      const float* __restrict__ xres,
                                                      const float* __restrict__ alpha,
                                                      float* __restrict__ out,
                                                      int b, int mbase) {
    extern __shared__ char dyn[];
    const int tid = threadIdx.x, w = tid >> 5;
    const int m0 = (mbase + blockIdx.x) * 128;

    uint32_t dynb = smem_u32(dyn);
    uint32_t base = (dynb + 255u) & ~255u;
    char* sb = dyn + (base - dynb);
    const uint32_t sbase = base;

    const __nv_bfloat16* pa = Aq + ((size_t)b * NPIX + m0) * (size_t)NPIX;
    const __nv_bfloat16* pb = VH + (size_t)b * CH * NPIX;

    auto issue_stage = [&](int t) {
        const int s = t % 3;
        const uint32_t dA = sbase + (uint32_t)s * PV_STAGE_B;
        const uint32_t dB = dA + 128 * LDT * 2;
        const int n0 = t << 6;
        #pragma unroll
        for (int p = 0; p < 4; ++p) {           // A: 128 rows x 64 bf16
            int idx = tid + p * 256;
            int row = idx >> 3, c8 = idx & 7;
            cpa16(dA + (uint32_t)(row * LDT + c8 * 8) * 2,
                  pa + (size_t)row * NPIX + n0 + c8 * 8);
        }
        #pragma unroll
        for (int p = 0; p < 8; ++p) {           // B: 256 rows x 64 bf16
            int idx = tid + p * 256;
            int row = idx >> 3, c8 = idx & 7;
            cpa16(dB + (uint32_t)(row * LDT + c8 * 8) * 2,
                  pb + (size_t)row * NPIX + n0 + c8 * 8);
        }
        cpa_commit();
    };

    const int wm = w >> 2;    // 0..1
    const int wc = w & 3;     // 0..3
    wmma::fragment<wmma::accumulator, 16, 16, 16, float> acc[4][4];
    #pragma unroll
    for (int mi = 0; mi < 4; ++mi)
        #pragma unroll
        for (int nj = 0; nj < 4; ++nj) wmma::fill_fragment(acc[mi][nj], 0.0f);

    issue_stage(0);
    issue_stage(1);
    issue_stage(2);

    for (int t = 0; t < 64; ++t) {
        if (t < 62) cpa_wait<2>();
        else if (t == 62) cpa_wait<1>();
        else cpa_wait<0>();
        __syncthreads();

        const __nv_bfloat16* cA = (const __nv_bfloat16*)(sb + (size_t)(t % 3) * PV_STAGE_B);
        const __nv_bfloat16* cB = cA + 128 * LDT;
        #pragma unroll
        for (int kk = 0; kk < 64; kk += 16) {
            wmma::fragment<wmma::matrix_a, 16, 16, 16, __nv_bfloat16, wmma::row_major> af[4];
            #pragma unroll
            for (int mi = 0; mi < 4; ++mi)
                wmma::load_matrix_sync(af[mi], cA + (wm * 64 + mi * 16) * LDT + kk, LDT);
            #pragma unroll
            for (int nj = 0; nj < 4; ++nj) {
                wmma::fragment<wmma::matrix_b, 16, 16, 16, __nv_bfloat16, wmma::col_major> bf;
                wmma::load_matrix_sync(bf, cB + (wc * 64 + nj * 16) * LDT + kk, LDT);
                #pragma unroll
                for (int mi = 0; mi < 4; ++mi)
                    wmma::mma_sync(acc[mi][nj], af[mi], bf, acc[mi][nj]);
            }
        }

        if (t + 3 < 64) issue_stage(t + 3);
    }

    // epilogue: stage acc in smem, out = x + base[c] - alpha*acc
    __syncthreads();
    float* Sep = (float*)sb;                     // 128 * LDE * 4 = 133,120 B
    #pragma unroll
    for (int mi = 0; mi < 4; ++mi)
        #pragma unroll
        for (int nj = 0; nj < 4; ++nj)
            wmma::store_matrix_sync(Sep + (wm * 64 + mi * 16) * LDE + wc * 64 + nj * 16,
                                    acc[mi][nj], LDE, wmma::mem_row_major);
    __syncthreads();

    const float al = alpha[0];
    const int ml = tid & 127;
    const int ch = tid >> 7;                     // 0..1
    #pragma unroll 4
    for (int c2 = 0; c2 < 128; ++c2) {
        int c = ch * 128 + c2;
        size_t o = ((size_t)b * CH + c) * NPIX + m0 + ml;
        out[o] = xres[o] + g_base[b * CH + c] - al * Sep[ml * LDE + c];
    }
}

// ---------------- launch ----------------
extern "C" void kernel_launch(void* const* d_in, const int* in_sizes, int n_in,
                              void* d_out, int out_size) {
    const float* x1    = (const float*)d_in[0];
    const float* x2    = (const float*)d_in[1];
    const float* x     = (const float*)d_in[2];
    const float* gamma = (const float*)d_in[3];
    const float* beta  = (const float*)d_in[4];
    const float* mean  = (const float*)d_in[5];
    const float* var   = (const float*)d_in[6];
    const float* Wb    = (const float*)d_in[7];
    const float* bb    = (const float*)d_in[8];
    const float* Wc    = (const float*)d_in[9];
    const float* bc    = (const float*)d_in[10];
    const float* Wd    = (const float*)d_in[11];
    const float* bd    = (const float*)d_in[12];
    const float* alpha = (const float*)d_in[13];
    float* out = (float*)d_out;

    __nv_bfloat16 *Qp, *Kp, *VHp, *Aqp;
    __half* Sp;
    cudaGetSymbolAddress((void**)&Qp,  g_Qb);
    cudaGetSymbolAddress((void**)&Kp,  g_Kb);
    cudaGetSymbolAddress((void**)&VHp, g_VH);
    cudaGetSymbolAddress((void**)&Sp,  g_S);
    cudaGetSymbolAddress((void**)&Aqp, g_Aq);

    cudaFuncSetAttribute(qk_wmma_kernel, cudaFuncAttributeMaxDynamicSharedMemorySize, QK_SMEM);
    cudaFuncSetAttribute(pv_wmma_kernel, cudaFuncAttributeMaxDynamicSharedMemorySize, PV_SMEM);
    cudaFuncSetAttribute(projv_kernel,  cudaFuncAttributeMaxDynamicSharedMemorySize, PJV_SMEM);

    // fork all side/half streams from capture root
    cudaEventRecord(g_evRoot, 0);
    cudaStreamWaitEvent(g_s2, g_evRoot, 0);
    for (int i = 0; i < BATCH * NHALF; ++i) cudaStreamWaitEvent(g_sH[i], g_evRoot, 0);

    // side stream: Wd transpose -> V projection; colsum -> base
    transwd_kernel<<<CH, CH, 0, g_s2>>>(Wd);
    colsum_kernel<<<dim3(CH, BATCH), 256, 0, g_s2>>>(x);
    sumv_kernel<<<BATCH, CH, 0, g_s2>>>(Wd, bd, alpha);
    projv_kernel<<<dim3(NPIX / 128, CH / 128, BATCH), 256, PJV_SMEM, g_s2>>>(x, bd, VHp);
    cudaEventRecord(g_evJ, g_s2);

    // weight prep on default stream
    prep_kernel<<<1, 256>>>(gamma, beta, mean, var);
    foldw_kernel<<<dim3(CKDIM, 2), 256>>>(Wb, bb, Wc, bc);
    cudaEventRecord(g_evW, 0);

    // per-batch, per-half pipelines
    const int IT = NPIX / 128;          // 32 i-tiles total
    const int ITH = IT / NHALF;         // 16 per half
    for (int b = 0; b < BATCH; ++b) {
        cudaStream_t s0 = g_sH[b * NHALF];
        cudaStreamWaitEvent(s0, g_evW, 0);
        projqk_kernel<<<dim3(NPIX / 128, 2), 256, 0, s0>>>(x1, x2, Qp, Kp, b);
        cudaEventRecord(g_evP[b], s0);
        for (int h = 0; h < NHALF; ++h) {
            cudaStream_t s = g_sH[b * NHALF + h];
            if (h > 0) cudaStreamWaitEvent(s, g_evP[b], 0);
            qk_wmma_kernel<<<dim3(IT, ITH), 256, QK_SMEM, s>>>(Qp, Kp, Sp, b, h * ITH);
            att_kernel<<<NPIX / NHALF, 256, 0, s>>>(Sp, Aqp, b, h * (NPIX / NHALF));
            cudaStreamWaitEvent(s, g_evJ, 0);
            pv_wmma_kernel<<<dim3(ITH), 256, PV_SMEM, s>>>(Aqp, VHp, x, alpha, out, b, h * ITH);
            cudaEventRecord(g_evH[b * NHALF + h], s);
        }
    }

    // join all half streams into the capture stream
    for (int i = 0; i < BATCH * NHALF; ++i) cudaStreamWaitEvent(0, g_evH[i], 0);
}